// round 7
// baseline (speedup 1.0000x reference)
#include <cuda_runtime.h>
#include <math.h>

#define NUM_EXPERTS 16
#define FREQ_BINS   2097152
#define ROW_V       (FREQ_BINS / 4)          // 524288 float4 per row = 2^19
#define TPB         256
#define ITERS       32                       // float4 stores per thread
#define BLOCKS_X    (ROW_V / (TPB * ITERS))  // 64 -> grid (64,16) = 1024 blocks
                                             // single wave on 148 SMs

// Single fused kernel, zero barriers, zero smem, one graph node.
//
// Per-warp head (redundant in all 8 warps of every block, all parallel at t=0
// since the grid is one wave):
//   * lanes 0..14 load the raw params and compute the double-precision
//     sigmoid (XLA logistic = 0.5 + 0.5*tanh(0.5x), cast f32 — byte-identical
//     to every passing round, rel_err always 0.0)
//   * rank each param among the 15 via a shfl compare loop (sigmoid is
//     strictly monotone, so ranking raw params == ranking sigmoids; ties give
//     identical sigmoids so tie order is irrelevant)
//   * expert e = blockIdx.y needs only the rank==e-1 and rank==e sigmoids:
//     fetch them with ballot+shfl. b[0]=0 / b[16]=1 endpoints become the
//     e==0 / e==15 special cases.
// Then the proven STG.128 write stream (measured 21.7-21.8us, ~6.4TB/s).
__global__ void __launch_bounds__(TPB) freq_bands_fused(
    const float* __restrict__ bp, float4* __restrict__ out)
{
    const unsigned FULL = 0xFFFFFFFFu;
    const int lane = threadIdx.x & 31;
    const int e    = blockIdx.y;

    // ---- head: two sigmoids for this expert, no sort, no barriers ----
    float p   = 0.0f;
    float sig = 0.0f;
    if (lane < NUM_EXPERTS - 1) {
        p = __ldg(&bp[lane]);
        sig = (float)(0.5 + 0.5 * tanh(0.5 * (double)p));
    }

    int rank = 0;
#pragma unroll
    for (int j = 0; j < NUM_EXPERTS - 1; j++) {
        float pj = __shfl_sync(FULL, p, j);
        if (lane < NUM_EXPERTS - 1 && (pj < p || (pj == p && j < lane))) rank++;
    }

    unsigned m_start = __ballot_sync(FULL, lane < NUM_EXPERTS - 1 && rank == e - 1);
    unsigned m_end   = __ballot_sync(FULL, lane < NUM_EXPERTS - 1 && rank == e);
    float sstart = __shfl_sync(FULL, sig, m_start ? (__ffs(m_start) - 1) : 0);
    float send   = __shfl_sync(FULL, sig, m_end   ? (__ffs(m_end)   - 1) : 0);

    const int s = (e == 0) ? 0 : (int)(sstart * 2097151.0f);   // f32 mul + trunc
    const int en = (e == NUM_EXPERTS - 1) ? FREQ_BINS
                                          : (int)(send * 2097151.0f);
    const unsigned len = (unsigned)(en - s);

    // ---- write stream (unchanged from the ceiling-measured config) ----
    float4* row = out + (size_t)e * ROW_V;
    const unsigned base = blockIdx.x * (TPB * ITERS) + threadIdx.x;

#pragma unroll
    for (int i = 0; i < ITERS; i++) {
        unsigned v = base + i * TPB;       // float4 index within the row
        int q = (int)(v << 2) - s;         // element offset relative to start
        float4 f;
        f.x = ((unsigned)(q    ) < len) ? 1.0f : 0.0f;
        f.y = ((unsigned)(q + 1) < len) ? 1.0f : 0.0f;
        f.z = ((unsigned)(q + 2) < len) ? 1.0f : 0.0f;
        f.w = ((unsigned)(q + 3) < len) ? 1.0f : 0.0f;
        row[v] = f;
    }
}

extern "C" void kernel_launch(void* const* d_in, const int* in_sizes, int n_in,
                              void* d_out, int out_size) {
    const float* bound_params = (const float*)d_in[0];
    float4* out = (float4*)d_out;

    dim3 grid(BLOCKS_X, NUM_EXPERTS);        // (64, 16) x 256 threads, one wave
    freq_bands_fused<<<grid, TPB>>>(bound_params, out);
}

// round 8
// speedup vs baseline: 1.1497x; 1.1497x over previous
#include <cuda_runtime.h>
#include <math.h>

#define NUM_EXPERTS 16
#define FREQ_BINS   2097152
#define ROW_V       (FREQ_BINS / 4)          // 524288 float4 per row = 2^19
#define TPB         256
#define ITERS       8
#define BLOCKS_X    (ROW_V / (TPB * ITERS))  // 256 -> grid (256,16) = 4096 (R4 proven)

__device__ int g_bounds[2 * NUM_EXPERTS];    // [start_e, end_e] pairs

// Fast double-precision sigmoid: 1/(1+exp(-x)).
// Custom short-chain exp: range-reduce by ln2 (hi/lo split), degree-10 Taylor
// over |f| <= 0.347 (remainder ~2^-42), exponent-splice 2^k. Total ~23
// dependent FP64 ops (~1100 cyc) vs libm tanh's ~60+ (~2.5us). Relative error
// ~1e-15 -> the f32 rounding is correctly rounded, bit-identical to the
// libm double-tanh path that measured rel_err=0.0 in every passing round.
__device__ __forceinline__ double fast_sigmoid_d(double x) {
    double y = -x;                                   // exp(-x)
    const double L2E    = 1.44269504088896340736;
    const double LN2_HI = 6.93147180369123816490e-01;
    const double LN2_LO = 1.90821492927058770002e-10;

    double kd = rint(y * L2E);
    int    k  = (int)kd;
    double f  = fma(-kd, LN2_HI, y);
    f         = fma(-kd, LN2_LO, f);

    // exp(f), Taylor to f^10/10!
    double p = 2.75573192239858906526e-07;           // 1/10!
    p = fma(p, f, 2.75573192239858906526e-06);       // 1/9!
    p = fma(p, f, 2.48015873015873015873e-05);       // 1/8!
    p = fma(p, f, 1.98412698412698412698e-04);       // 1/7!
    p = fma(p, f, 1.38888888888888888889e-03);       // 1/6!
    p = fma(p, f, 8.33333333333333333333e-03);       // 1/5!
    p = fma(p, f, 4.16666666666666666667e-02);       // 1/4!
    p = fma(p, f, 1.66666666666666666667e-01);       // 1/3!
    p = fma(p, f, 5.00000000000000000000e-01);       // 1/2!
    p = fma(p, f, 1.0);
    p = fma(p, f, 1.0);

    // scale by 2^k (|x| of normal params < ~6, so k in a tiny safe range)
    double scale = __hiloint2double((1023 + k) << 20, 0);
    double e = p * scale;

    return 1.0 / (1.0 + e);
}

// Prep: ONE warp, no smem. Lanes 0..14 compute sigmoids in parallel with the
// short FP64 chain above. Lane 0 gathers via shfl, sorts 17 values, writes
// bounds, fences, then TRIGGERS the PDL dependency so masks unparks before
// this kernel's teardown.
__global__ void prep_kernel(const float* __restrict__ bp) {
    const int lane = threadIdx.x;

    float my = 0.0f;
    if (lane < NUM_EXPERTS - 1) {
        my = (float)fast_sigmoid_d((double)bp[lane]);
    }

    float b[NUM_EXPERTS + 1];
    b[0] = 0.0f;
    b[NUM_EXPERTS] = 1.0f;
#pragma unroll
    for (int i = 0; i < NUM_EXPERTS - 1; i++)
        b[i + 1] = __shfl_sync(0xFFFFFFFFu, my, i);

    if (lane == 0) {
        for (int i = 1; i <= NUM_EXPERTS; i++) {     // insertion sort, 17 elems
            float key = b[i];
            int j = i - 1;
            while (j >= 0 && b[j] > key) { b[j + 1] = b[j]; j--; }
            b[j + 1] = key;
        }
#pragma unroll
        for (int e = 0; e < NUM_EXPERTS; e++) {
            g_bounds[2 * e]     = (int)(b[e] * 2097151.0f);   // f32 mul + trunc
            g_bounds[2 * e + 1] = (e < NUM_EXPERTS - 1)
                                    ? (int)(b[e + 1] * 2097151.0f)
                                    : FREQ_BINS;
        }
        __threadfence();
#if __CUDA_ARCH__ >= 900
        cudaTriggerProgrammaticLaunchCompletion();
#endif
    }
}

// Pure STG.128 write stream — R4's exact proven config (21.7us, ~6.4TB/s).
__global__ void __launch_bounds__(TPB) masks_kernel(float4* __restrict__ out) {
#if __CUDA_ARCH__ >= 900
    cudaGridDependencySynchronize();
#endif
    const int e  = blockIdx.y;
    const int s  = g_bounds[2 * e];
    const unsigned len = (unsigned)(g_bounds[2 * e + 1] - s);

    float4* row = out + (size_t)e * ROW_V;
    const unsigned base = blockIdx.x * (TPB * ITERS) + threadIdx.x;

#pragma unroll
    for (int i = 0; i < ITERS; i++) {
        unsigned v = base + i * TPB;       // float4 index within the row
        int p = (int)(v << 2) - s;         // element offset relative to start
        float4 f;
        f.x = ((unsigned)(p    ) < len) ? 1.0f : 0.0f;
        f.y = ((unsigned)(p + 1) < len) ? 1.0f : 0.0f;
        f.z = ((unsigned)(p + 2) < len) ? 1.0f : 0.0f;
        f.w = ((unsigned)(p + 3) < len) ? 1.0f : 0.0f;
        row[v] = f;
    }
}

extern "C" void kernel_launch(void* const* d_in, const int* in_sizes, int n_in,
                              void* d_out, int out_size) {
    const float* bound_params = (const float*)d_in[0];
    float4* out = (float4*)d_out;

    prep_kernel<<<1, 32>>>(bound_params);

    // PDL: masks pre-launches, parks at cudaGridDependencySynchronize until
    // prep's explicit trigger (bounds written + fenced).
    cudaLaunchConfig_t cfg = {};
    cfg.gridDim  = dim3(BLOCKS_X, NUM_EXPERTS);
    cfg.blockDim = dim3(TPB);
    cudaLaunchAttribute attr[1];
    attr[0].id = cudaLaunchAttributeProgrammaticStreamSerialization;
    attr[0].val.programmaticStreamSerializationAllowed = 1;
    cfg.attrs    = attr;
    cfg.numAttrs = 1;
    cudaLaunchKernelEx(&cfg, masks_kernel, out);
}